// round 2
// baseline (speedup 1.0000x reference)
#include <cuda_runtime.h>
#include <math.h>

// EnhancedFinancialGAT collapses: initial node features are uniform across all
// N nodes per batch item, so GAT attention weights (which sum to 1 per dst)
// aggregate identical messages -> each layer is just relu(W @ g + b), uniform
// over nodes. The whole model is a small per-item MLP:
//   h   = relu(W_in x + b_in)                     [256]
//   g_l = relu(gat_W[l] g + gat_b[l])  l=0..2     [256]
//   f   = relu(W_fuse [g; emb[ci]] + b_fuse)      [256]  (input 320)
//   p   = relu(W_p1 f)->relu(W_p2)->W_p3          price
//   d   = relu(W_d1 f)->relu(W_d2)->sigmoid(W_d3) direction

#define HIDDEN 256
#define IN_DIM 64
#define EMB_DIM 64
#define FUSE_IN 320

__device__ __forceinline__ float dotv(const float* __restrict__ w,
                                      const float* __restrict__ v, int n) {
    const float4* w4 = reinterpret_cast<const float4*>(w);
    const float4* v4 = reinterpret_cast<const float4*>(v);
    float acc = 0.f;
#pragma unroll 4
    for (int i = 0; i < n / 4; i++) {
        float4 a = w4[i];
        float4 b = v4[i];
        acc = fmaf(a.x, b.x, acc);
        acc = fmaf(a.y, b.y, acc);
        acc = fmaf(a.z, b.z, acc);
        acc = fmaf(a.w, b.w, acc);
    }
    return acc;
}

__global__ __launch_bounds__(256, 8)
void gat_collapse_kernel(
    const float* __restrict__ x,            // [64,64]
    const int*   __restrict__ company_idx,  // [64]
    const float* __restrict__ W_in,         // [256,64]
    const float* __restrict__ b_in,         // [256]
    const float* __restrict__ gat_W,        // [3,256,256]
    const float* __restrict__ gat_b,        // [3,256]
    const float* __restrict__ emb,          // [2000,64]
    const float* __restrict__ W_fuse,       // [256,320]
    const float* __restrict__ b_fuse,       // [256]
    const float* __restrict__ W_p1, const float* __restrict__ b_p1,  // [128,256],[128]
    const float* __restrict__ W_p2, const float* __restrict__ b_p2,  // [64,128],[64]
    const float* __restrict__ W_p3, const float* __restrict__ b_p3,  // [1,64],[1]
    const float* __restrict__ W_d1, const float* __restrict__ b_d1,
    const float* __restrict__ W_d2, const float* __restrict__ b_d2,
    const float* __restrict__ W_d3, const float* __restrict__ b_d3,
    float* __restrict__ out, int B)
{
    const int b   = blockIdx.x;
    const int tid = threadIdx.x;

    __shared__ __align__(16) float sA[FUSE_IN];   // activations / fuse input
    __shared__ __align__(16) float sB[HIDDEN];    // activations
    __shared__ __align__(16) float sC[128];       // p1 out
    __shared__ __align__(16) float sD[128];       // d1 out (0:128), then p2/d2
    __shared__ __align__(16) float sP2[64];
    __shared__ __align__(16) float sD2[64];

    // 1. load x row
    if (tid < IN_DIM) sA[tid] = x[b * IN_DIM + tid];
    __syncthreads();

    // 2. h = relu(W_in x + b_in)  -> sB
    {
        float v = dotv(W_in + tid * IN_DIM, sA, IN_DIM) + b_in[tid];
        sB[tid] = fmaxf(v, 0.f);
    }
    __syncthreads();

    // 3. GAT layer 0: sB -> sA
    {
        float v = dotv(gat_W + 0 * HIDDEN * HIDDEN + tid * HIDDEN, sB, HIDDEN) + gat_b[0 * HIDDEN + tid];
        sA[tid] = fmaxf(v, 0.f);
    }
    __syncthreads();
    // layer 1: sA -> sB
    {
        float v = dotv(gat_W + 1 * HIDDEN * HIDDEN + tid * HIDDEN, sA, HIDDEN) + gat_b[1 * HIDDEN + tid];
        sB[tid] = fmaxf(v, 0.f);
    }
    __syncthreads();
    // layer 2: sB -> sA[0:256]; append emb row -> sA[256:320]
    {
        float v = dotv(gat_W + 2 * HIDDEN * HIDDEN + tid * HIDDEN, sB, HIDDEN) + gat_b[2 * HIDDEN + tid];
        sA[tid] = fmaxf(v, 0.f);
    }
    if (tid < EMB_DIM) {
        int ci = company_idx[b];
        sA[HIDDEN + tid] = emb[ci * EMB_DIM + tid];
    }
    __syncthreads();

    // 4. fused = relu(W_fuse [g;emb] + b_fuse) -> sB
    {
        float v = dotv(W_fuse + tid * FUSE_IN, sA, FUSE_IN) + b_fuse[tid];
        sB[tid] = fmaxf(v, 0.f);
    }
    __syncthreads();

    // 5. p1 (threads 0..127) and d1 (threads 128..255) concurrently
    if (tid < 128) {
        float v = dotv(W_p1 + tid * HIDDEN, sB, HIDDEN) + b_p1[tid];
        sC[tid] = fmaxf(v, 0.f);
    } else {
        int o = tid - 128;
        float v = dotv(W_d1 + o * HIDDEN, sB, HIDDEN) + b_d1[o];
        sD[o] = fmaxf(v, 0.f);
    }
    __syncthreads();

    // 6. p2 (threads 0..63) and d2 (threads 64..127) concurrently
    if (tid < 64) {
        float v = dotv(W_p2 + tid * 128, sC, 128) + b_p2[tid];
        sP2[tid] = fmaxf(v, 0.f);
    } else if (tid < 128) {
        int o = tid - 64;
        float v = dotv(W_d2 + o * 128, sD, 128) + b_d2[o];
        sD2[o] = fmaxf(v, 0.f);
    }
    __syncthreads();

    // 7. heads: warp 0 lane 0 -> price, warp 1 lane 0 -> direction
    if (tid == 0) {
        float acc = dotv(W_p3, sP2, 64) + b_p3[0];
        out[b] = acc;                       // price
    } else if (tid == 32) {
        float acc = dotv(W_d3, sD2, 64) + b_d3[0];
        out[64 + b] = 1.f / (1.f + expf(-acc));  // direction (sigmoid)
    }
}

extern "C" void kernel_launch(void* const* d_in, const int* in_sizes, int n_in,
                              void* d_out, int out_size) {
    // metadata order:
    // 0 x, 1 company_indices, 2 edge_index, 3 edge_attr,
    // 4 W_in, 5 b_in, 6 gat_W, 7 gat_att_src, 8 gat_att_dst, 9 gat_We,
    // 10 gat_att_edge, 11 gat_b, 12 emb, 13 W_fuse, 14 b_fuse,
    // 15 W_p1, 16 b_p1, 17 W_p2, 18 b_p2, 19 W_p3, 20 b_p3,
    // 21 W_d1, 22 b_d1, 23 W_d2, 24 b_d2, 25 W_d3, 26 b_d3
    const float* x        = (const float*)d_in[0];
    const int*   ci       = (const int*)  d_in[1];
    const float* W_in     = (const float*)d_in[4];
    const float* b_in     = (const float*)d_in[5];
    const float* gat_W    = (const float*)d_in[6];
    const float* gat_b    = (const float*)d_in[11];
    const float* emb      = (const float*)d_in[12];
    const float* W_fuse   = (const float*)d_in[13];
    const float* b_fuse   = (const float*)d_in[14];
    const float* W_p1     = (const float*)d_in[15];
    const float* b_p1     = (const float*)d_in[16];
    const float* W_p2     = (const float*)d_in[17];
    const float* b_p2     = (const float*)d_in[18];
    const float* W_p3     = (const float*)d_in[19];
    const float* b_p3     = (const float*)d_in[20];
    const float* W_d1     = (const float*)d_in[21];
    const float* b_d1     = (const float*)d_in[22];
    const float* W_d2     = (const float*)d_in[23];
    const float* b_d2     = (const float*)d_in[24];
    const float* W_d3     = (const float*)d_in[25];
    const float* b_d3     = (const float*)d_in[26];

    const int B = in_sizes[0] / IN_DIM;  // 64

    gat_collapse_kernel<<<B, 256>>>(
        x, ci, W_in, b_in, gat_W, gat_b, emb, W_fuse, b_fuse,
        W_p1, b_p1, W_p2, b_p2, W_p3, b_p3,
        W_d1, b_d1, W_d2, b_d2, W_d3, b_d3,
        (float*)d_out, B);
}